// round 13
// baseline (speedup 1.0000x reference)
#include <cuda_runtime.h>
#include <cuda_fp16.h>
#include <cstdint>
#include <math.h>

// Problem constants
#define BATCH 4
#define SEQ   2048
#define DMODEL 512
#define NHEAD 8
#define DHEAD 64
#define DFF   2048
#define MROWS (BATCH * SEQ)   // 8192

// ---------------------------------------------------------------------------
// Scratch (allocation-free: __device__ globals) — activations fp16
// ---------------------------------------------------------------------------
__device__ uint16_t g_h  [(size_t)MROWS * DMODEL];
__device__ uint16_t g_q  [(size_t)MROWS * DMODEL];
__device__ uint16_t g_qkv[(size_t)MROWS * (3 * DMODEL)];   // fused q|k|v, stride 1536
__device__ uint16_t g_kv [(size_t)MROWS * (2 * DMODEL)];   // fused k|v, stride 1024
__device__ uint16_t g_att[(size_t)MROWS * DMODEL];
__device__ uint16_t g_enc[(size_t)MROWS * DMODEL];
__device__ float    g_x1 [(size_t)MROWS * DMODEL];
__device__ float    g_x2 [(size_t)MROWS * DMODEL];
__device__ uint16_t g_ff [(size_t)MROWS * DFF];
// converted weights, fp16 [N][K]: 8x 512x512, ff1(2048x512), ff2(512x2048)
#define WOFF_FF1 2097152
#define WOFF_FF2 3145728
__device__ uint16_t g_w[4194304];

// ---------------------------------------------------------------------------
// Helpers
// ---------------------------------------------------------------------------
__device__ __forceinline__ uint32_t smem_u32(const void* p) {
    uint32_t a;
    asm("{ .reg .u64 t; cvta.to.shared.u64 t, %1; cvt.u32.u64 %0, t; }"
        : "=r"(a) : "l"(p));
    return a;
}

__device__ __forceinline__ void ldm_x4(uint32_t* r, const void* p) {
    uint32_t a = smem_u32(p);
    asm volatile("ldmatrix.sync.aligned.m8n8.x4.shared.b16 {%0,%1,%2,%3}, [%4];"
        : "=r"(r[0]), "=r"(r[1]), "=r"(r[2]), "=r"(r[3]) : "r"(a));
}

// D += A(16x16,row) * B(16x8,col)  fp16 in, fp32 acc
__device__ __forceinline__ void mma_f16(float* d, const uint32_t* a,
                                        uint32_t b0, uint32_t b1) {
    asm("mma.sync.aligned.m16n8k16.row.col.f32.f16.f16.f32 "
        "{%0,%1,%2,%3}, {%4,%5,%6,%7}, {%8,%9}, {%0,%1,%2,%3};"
        : "+f"(d[0]), "+f"(d[1]), "+f"(d[2]), "+f"(d[3])
        : "r"(a[0]), "r"(a[1]), "r"(a[2]), "r"(a[3]), "r"(b0), "r"(b1));
}

// D += A * B, fp16 in, fp16 acc (d = 2x uint32 = 4 halves)
__device__ __forceinline__ void mma_f16acc(uint32_t* d, const uint32_t* a,
                                           uint32_t b0, uint32_t b1) {
    asm("mma.sync.aligned.m16n8k16.row.col.f16.f16.f16.f16 "
        "{%0,%1}, {%2,%3,%4,%5}, {%6,%7}, {%0,%1};"
        : "+r"(d[0]), "+r"(d[1])
        : "r"(a[0]), "r"(a[1]), "r"(a[2]), "r"(a[3]), "r"(b0), "r"(b1));
}

__device__ __forceinline__ void cp16(uint32_t dst, const void* src) {
    asm volatile("cp.async.cg.shared.global [%0], [%1], 16;" :: "r"(dst), "l"(src));
}
#define CP_COMMIT() asm volatile("cp.async.commit_group;" ::: "memory")
#define CP_WAIT2()  asm volatile("cp.async.wait_group 2;" ::: "memory")

__device__ __forceinline__ uint32_t pack_half(float a, float b) {
    __half2 h = __floats2half2_rn(a, b);
    return *reinterpret_cast<uint32_t*>(&h);
}

__device__ __forceinline__ float2 unpack_half(uint32_t v) {
    __half2 h = *reinterpret_cast<__half2*>(&v);
    return __half22float2(h);
}

__device__ __forceinline__ uint2 cvt4_half(float4 a) {
    uint2 r;
    r.x = pack_half(a.x, a.y);
    r.y = pack_half(a.z, a.w);
    return r;
}

// Fast exp on FMA/ALU pipes (no MUFU). ~2e-6 rel err.
__device__ __forceinline__ float fexp(float x) {
    x = fmaxf(x, -80.f);
    float t = fmaf(x, 1.442695041f, 12582912.f);
    int   n = __float_as_int(t) - 0x4B400000;
    float i_f = t - 12582912.f;
    float f = fmaf(x, 1.442695041f, -i_f);
    float p = 0.0013333558f;
    p = fmaf(p, f, 0.0096181291f);
    p = fmaf(p, f, 0.0555041087f);
    p = fmaf(p, f, 0.2402265069f);
    p = fmaf(p, f, 0.6931471806f);
    p = fmaf(p, f, 1.0f);
    return __int_as_float(__float_as_int(p) + (n << 23));
}

// ---------------------------------------------------------------------------
// Weight conversion: W[K][N] fp32 -> [N][K] fp16
// ---------------------------------------------------------------------------
struct WPtrs8 { const float* p[8]; };

__global__ void wconv8_kernel(WPtrs8 ws, uint16_t* __restrict__ Wh)
{
    __shared__ float tile[32][33];
    const int K = 512, N = 512;
    const float* W = ws.p[blockIdx.z];
    uint16_t* wh = Wh + (size_t)blockIdx.z * 262144;
    int n0 = blockIdx.x * 32, k0 = blockIdx.y * 32;
    int tx = threadIdx.x, ty = threadIdx.y;
    #pragma unroll
    for (int i = 0; i < 4; i++)
        tile[ty + i * 8][tx] = W[(size_t)(k0 + ty + i * 8) * N + n0 + tx];
    __syncthreads();
    #pragma unroll
    for (int i = 0; i < 4; i++) {
        int n = ty + i * 8;
        wh[(size_t)(n0 + n) * K + k0 + tx] =
            __half_as_ushort(__float2half_rn(tile[tx][n]));
    }
}

__global__ void wconv_kernel(const float* __restrict__ W,
                             uint16_t* __restrict__ Wh, int K, int N)
{
    __shared__ float tile[32][33];
    int n0 = blockIdx.x * 32, k0 = blockIdx.y * 32;
    int tx = threadIdx.x, ty = threadIdx.y;
    #pragma unroll
    for (int i = 0; i < 4; i++)
        tile[ty + i * 8][tx] = W[(size_t)(k0 + ty + i * 8) * N + n0 + tx];
    __syncthreads();
    #pragma unroll
    for (int i = 0; i < 4; i++) {
        int n = ty + i * 8;
        Wh[(size_t)(n0 + n) * K + k0 + tx] =
            __half_as_ushort(__float2half_rn(tile[tx][n]));
    }
}

// fp32 activations -> fp16 (identity, for encoder_output)
__global__ void split_kernel(const float* __restrict__ x,
                             uint16_t* __restrict__ out)
{
    int row = blockIdx.x;
    int t = threadIdx.x;  // 0..127
    const float4 v = ((const float4*)(x + (size_t)row * DMODEL))[t];
    *(uint2*)(out + (size_t)row * DMODEL + t * 4) = cvt4_half(v);
}

// ---------------------------------------------------------------------------
// LayerNorm -> fp16 output
// ---------------------------------------------------------------------------
__global__ void ln_kernel(const float* __restrict__ x,
                          const float* __restrict__ g,
                          const float* __restrict__ b,
                          uint16_t* __restrict__ out)
{
    int row = blockIdx.x;
    int t = threadIdx.x;  // 0..127
    const float4 v = ((const float4*)(x + (size_t)row * DMODEL))[t];

    __shared__ float red1[4], red2[4];

    float s = v.x + v.y + v.z + v.w;
    #pragma unroll
    for (int o = 16; o; o >>= 1) s += __shfl_xor_sync(0xffffffffu, s, o);
    if ((t & 31) == 0) red1[t >> 5] = s;
    __syncthreads();
    float mean = (red1[0] + red1[1] + red1[2] + red1[3]) * (1.0f / DMODEL);

    float d0 = v.x - mean, d1 = v.y - mean, d2 = v.z - mean, d3 = v.w - mean;
    float sq = d0*d0 + d1*d1 + d2*d2 + d3*d3;
    #pragma unroll
    for (int o = 16; o; o >>= 1) sq += __shfl_xor_sync(0xffffffffu, sq, o);
    if ((t & 31) == 0) red2[t >> 5] = sq;
    __syncthreads();
    float var = (red2[0] + red2[1] + red2[2] + red2[3]) * (1.0f / (DMODEL - 1));
    float rstd = 1.0f / (sqrtf(var) + 1e-6f);

    const float4 gv = ((const float4*)g)[t];
    const float4 bv = ((const float4*)b)[t];
    float4 o4;
    o4.x = gv.x * d0 * rstd + bv.x;
    o4.y = gv.y * d1 * rstd + bv.y;
    o4.z = gv.z * d2 * rstd + bv.z;
    o4.w = gv.w * d3 * rstd + bv.w;
    *(uint2*)(out + (size_t)row * DMODEL + t * 4) = cvt4_half(o4);
}

// ---------------------------------------------------------------------------
// GEMM v5 (best measured): 128x128 tile, BK=32, fp16 in, fp32 acc,
// 3-stage cp.async, B-fragment ping-pong.
// ---------------------------------------------------------------------------
#define LDA 40
#define GSMEM (3 * 20480)

template<int OUT, bool BIAS, bool RES, bool RELU>
__global__ void __launch_bounds__(256, 2)
gemm_v5(const uint16_t* __restrict__ A_g, const uint16_t* __restrict__ B_g,
        const float* __restrict__ bias, const float* __restrict__ res,
        float* __restrict__ Cf, uint16_t* __restrict__ Ch,
        int M, int N, int K)
{
    extern __shared__ char smem[];
    const uint32_t sbase = smem_u32(smem);

    const int tid  = threadIdx.x;
    const int lane = tid & 31;
    const int wid  = tid >> 5;
    const int m0 = blockIdx.y * 128;
    const int n0 = blockIdx.x * 128;
    const int wm = (wid >> 1) * 32;
    const int wn = (wid & 1) * 64;
    const int KT = K >> 5;

    float acc[2][8][4];
    #pragma unroll
    for (int i = 0; i < 2; i++)
        #pragma unroll
        for (int j = 0; j < 8; j++)
            #pragma unroll
            for (int c = 0; c < 4; c++) acc[i][j][c] = 0.f;

    const int lrow = tid >> 1;
    const int lc0  = (tid & 1) * 2;

    auto issue = [&](int kt) {
        int st = kt % 3;
        uint32_t base = sbase + st * 20480;
        size_t aoff = (size_t)(m0 + lrow) * K + kt * 32 + lc0 * 8;
        size_t boff = (size_t)(n0 + lrow) * K + kt * 32 + lc0 * 8;
        uint32_t d = base + lrow * 80 + lc0 * 16;
        cp16(d,              A_g + aoff);
        cp16(d + 16,         A_g + aoff + 8);
        cp16(d + 10240,      B_g + boff);
        cp16(d + 10240 + 16, B_g + boff + 8);
    };

    issue(0);
    CP_COMMIT();
    if (KT > 1) issue(1);
    CP_COMMIT();

    const int lr = lane & 15;
    const int lh = (lane >> 4) * 8;

    for (int kt = 0; kt < KT; kt++) {
        if (kt + 2 < KT) issue(kt + 2);
        CP_COMMIT();
        CP_WAIT2();
        __syncthreads();

        const uint16_t* As = (const uint16_t*)(smem + (kt % 3) * 20480);
        const uint16_t* Bs = As + 5120;

        #pragma unroll
        for (int ks = 0; ks < 32; ks += 16) {
            uint32_t af[2][4];
            #pragma unroll
            for (int mi = 0; mi < 2; mi++)
                ldm_x4(af[mi], As + (wm + mi * 16 + lr) * LDA + ks + lh);

            uint32_t bf[2][4];
            ldm_x4(bf[0], Bs + (wn + lr) * LDA + ks + lh);
            #pragma unroll
            for (int ni = 0; ni < 4; ni++) {
                const int cur = ni & 1;
                if (ni < 3)
                    ldm_x4(bf[cur ^ 1], Bs + (wn + (ni + 1) * 16 + lr) * LDA + ks + lh);
                #pragma unroll
                for (int mi = 0; mi < 2; mi++) {
                    mma_f16(acc[mi][ni * 2],     af[mi], bf[cur][0], bf[cur][2]);
                    mma_f16(acc[mi][ni * 2 + 1], af[mi], bf[cur][1], bf[cur][3]);
                }
            }
        }
        __syncthreads();
    }

    const int er = lane >> 2;
    const int ec = (lane & 3) * 2;
    #pragma unroll
    for (int mi = 0; mi < 2; mi++) {
        #pragma unroll
        for (int nf = 0; nf < 8; nf++) {
            int gm0 = m0 + wm + mi * 16 + er;
            int gn  = n0 + wn + nf * 8 + ec;
            #pragma unroll
            for (int half = 0; half < 2; half++) {
                int gm = gm0 + half * 8;
                float cx = acc[mi][nf][half * 2];
                float cy = acc[mi][nf][half * 2 + 1];
                if (BIAS) { cx += bias[gn]; cy += bias[gn + 1]; }
                if (RES) {
                    const float2 rv = *(const float2*)(res + (size_t)gm * N + gn);
                    cx += rv.x; cy += rv.y;
                }
                if (RELU) { cx = fmaxf(cx, 0.f); cy = fmaxf(cy, 0.f); }
                size_t idx = (size_t)gm * N + gn;
                if (OUT == 0) {
                    *(float2*)(Cf + idx) = make_float2(cx, cy);
                } else {
                    *(uint32_t*)(Ch + idx) = pack_half(cx, cy);
                }
            }
        }
    }
}

// ---------------------------------------------------------------------------
// Flash attention v3 (FA2 warp layout): each warp owns 16 full q-rows.
// QK f16-acc; P stays in registers (C-frag == A-frag trick); PV fp32 acc.
// m/l/alpha in registers; 2 syncs per key tile; no Ps smem.
// smem: Qs @0 (18432), Ks @18432 (18432), Vt @36864 (17408) = 54272.
// ---------------------------------------------------------------------------
#define QLD 72
#define PLD 136
#define ATT3_SMEM 54272

template<bool CAUSAL>
__global__ void __launch_bounds__(256, 2)
attn_v3(const uint16_t* __restrict__ Q, int ldq,
        const uint16_t* __restrict__ K, int ldk,
        const uint16_t* __restrict__ V, int ldv,
        uint16_t* __restrict__ O)
{
    extern __shared__ char asmem[];
    uint16_t* Qs = (uint16_t*)(asmem);
    uint16_t* Ks = (uint16_t*)(asmem + 18432);
    uint16_t* Vt = (uint16_t*)(asmem + 36864);

    const int tid  = threadIdx.x;
    const int lane = tid & 31;
    const int wid  = tid >> 5;
    const int wq   = wid * 16;          // warp's q-row base within tile
    const int er   = lane >> 2;
    const int ec   = (lane & 3) * 2;
    const int lr   = lane & 15;
    const int lh   = (lane >> 4) * 8;

    const int qt = CAUSAL ? ((int)gridDim.x - 1 - (int)blockIdx.x) : (int)blockIdx.x;
    const int q0 = qt * 128;
    const int h  = blockIdx.y;
    const int b  = blockIdx.z;

    const size_t bq  = ((size_t)b * SEQ + q0) * ldq + (size_t)h * DHEAD;
    const size_t bk  = ((size_t)b * SEQ) * ldk + (size_t)h * DHEAD;
    const size_t bvo = ((size_t)b * SEQ) * ldv + (size_t)h * DHEAD;

    // ---- stage Q, frag once ----
    #pragma unroll
    for (int it = 0; it < 4; it++) {
        int vI = tid + it * 256;
        int row = vI >> 3, c8 = vI & 7;
        uint4 qv = *(const uint4*)(Q + bq + (size_t)row * ldq + c8 * 8);
        *(uint4*)(Qs + row * QLD + c8 * 8) = qv;
    }
    __syncthreads();
    uint32_t aq[4][4];
    #pragma unroll
    for (int kg = 0; kg < 4; kg++)
        ldm_x4(aq[kg], Qs + (wq + lr) * QLD + kg * 16 + lh);

    float of[8][4];
    #pragma unroll
    for (int ng = 0; ng < 8; ng++)
        #pragma unroll
        for (int c = 0; c < 4; c++) of[ng][c] = 0.f;

    float m1 = -1e30f, m2 = -1e30f, l1 = 0.f, l2 = 0.f;

    const int ntiles = CAUSAL ? (qt + 1) : (SEQ / 128);

    for (int t = 0; t < ntiles; t++) {
        const int j0 = t * 128;

        // ---- load K tile [128][64] and V tile (transposed [d][j]) ----
        #pragma unroll
        for (int it = 0; it < 4; it++) {
            int vI = tid + it * 256;
            int row = vI >> 3, c8 = vI & 7;
            uint4 kv = *(const uint4*)(K + bk + (size_t)(j0 + row) * ldk + c8 * 8);
            *(uint4*)(Ks + row * QLD + c8 * 8) = kv;
        }
        #pragma unroll
        for (int it = 0; it < 8; it++) {
            int vI = tid + it * 256;
            int row = vI >> 4, c4 = vI & 15;
            uint2 vv = *(const uint2*)(V + bvo + (size_t)(j0 + row) * ldv + c4 * 4);
            Vt[(c4 * 4 + 0) * PLD + row] = (uint16_t)(vv.x & 0xffff);
            Vt[(c4 * 4 + 1) * PLD + row] = (uint16_t)(vv.x >> 16);
            Vt[(c4 * 4 + 2) * PLD + row] = (uint16_t)(vv.y & 0xffff);
            Vt[(c4 * 4 + 3) * PLD + row] = (uint16_t)(vv.y >> 16);
        }
        __syncthreads();   // (A) tiles visible

        // ---- QK^T: warp computes 16q x 128k, f16 acc ----
        uint32_t sch[16][2];
        #pragma unroll
        for (int g = 0; g < 16; g++) { sch[g][0] = 0u; sch[g][1] = 0u; }

        #pragma unroll
        for (int kg = 0; kg < 4; kg++) {
            #pragma unroll
            for (int ng = 0; ng < 8; ng++) {
                uint32_t bk4[4];
                ldm_x4(bk4, Ks + (ng * 16 + lr) * QLD + kg * 16 + lh);
                mma_f16acc(sch[ng * 2],     aq[kg], bk4[0], bk4[2]);
                mma_f16acc(sch[ng * 2 + 1], aq[kg], bk4[1], bk4[3]);
            }
        }

        // ---- softmax, all in registers ----
        // pass 1: scale + mask, running max, repack
        float tm1 = -1e30f, tm2 = -1e30f;
        const int gq1 = q0 + wq + er;
        const int gq2 = gq1 + 8;
        #pragma unroll
        for (int g = 0; g < 16; g++) {
            float2 lo = unpack_half(sch[g][0]);
            float2 hi = unpack_half(sch[g][1]);
            float v0 = lo.x * 0.125f, v1 = lo.y * 0.125f;
            float v2 = hi.x * 0.125f, v3 = hi.y * 0.125f;
            if (CAUSAL && t == qt) {
                int gj = j0 + g * 8 + ec;
                if (gj     > gq1) v0 = -30000.f;
                if (gj + 1 > gq1) v1 = -30000.f;
                if (gj     > gq2) v2 = -30000.f;
                if (gj + 1 > gq2) v3 = -30000.f;
            }
            tm1 = fmaxf(tm1, fmaxf(v0, v1));
            tm2 = fmaxf(tm2, fmaxf(v2, v3));
            sch[g][0] = pack_half(v0, v1);
            sch[g][1] = pack_half(v2, v3);
        }
        tm1 = fmaxf(tm1, __shfl_xor_sync(0xffffffffu, tm1, 1));
        tm1 = fmaxf(tm1, __shfl_xor_sync(0xffffffffu, tm1, 2));
        tm2 = fmaxf(tm2, __shfl_xor_sync(0xffffffffu, tm2, 1));
        tm2 = fmaxf(tm2, __shfl_xor_sync(0xffffffffu, tm2, 2));

        float mn1 = fmaxf(m1, tm1), mn2 = fmaxf(m2, tm2);
        float al1 = fexp(m1 - mn1), al2 = fexp(m2 - mn2);
        m1 = mn1; m2 = mn2;

        // pass 2: exp, row sums, repack P (in place)
        float ts1 = 0.f, ts2 = 0.f;
        #pragma unroll
        for (int g = 0; g < 16; g++) {
            float2 lo = unpack_half(sch[g][0]);
            float2 hi = unpack_half(sch[g][1]);
            float p0 = fexp(lo.x - mn1);
            float p1 = fexp(lo.y - mn1);
            float p2 = fexp(hi.x - mn2);
            float p3 = fexp(hi.y - mn2);
            ts1 += p0 + p1;
            ts2 += p2 + p3;
            sch[g][0] = pack_half(p0, p1);
            sch[g][1] = pack_half(p2, p3);
        }
        ts1 += __shfl_xor_sync(0xffffffffu, ts1, 1);
        ts1 += __shfl_xor_sync(0xffffffffu, ts1, 2);
        ts2 += __shfl_xor_sync(0xffffffffu, ts2, 1);
        ts2 += __shfl_xor_sync(0xffffffffu, ts2, 2);
        l1 = l1 * al1 + ts1;
        l2 = l2 * al2 + ts2;

        // rescale O accumulators
        #pragma unroll
        for (int ng = 0; ng < 8; ng++) {
            of[ng][0] *= al1; of[ng][1] *= al1;
            of[ng][2] *= al2; of[ng][3] *= al2;
        }

        // ---- PV: P (registers, C-frag == A-frag) x V (smem), fp32 acc ----
        #pragma unroll
        for (int kg = 0; kg < 8; kg++) {
            uint32_t a4[4] = {sch[2 * kg][0], sch[2 * kg][1],
                              sch[2 * kg + 1][0], sch[2 * kg + 1][1]};
            #pragma unroll
            for (int ng = 0; ng < 4; ng++) {
                uint32_t bv4[4];
                ldm_x4(bv4, Vt + (ng * 16 + lr) * PLD + kg * 16 + lh);
                mma_f16(of[ng * 2],     a4, bv4[0], bv4[2]);
                mma_f16(of[ng * 2 + 1], a4, bv4[1], bv4[3]);
            }
        }
        __syncthreads();   // (B) reads done before next tile's writes
    }

    // ---- epilogue ----
    const float inv1 = 1.0f / l1;
    const float inv2 = 1.0f / l2;
    const int gq = q0 + wq + er;
    #pragma unroll
    for (int ng = 0; ng < 8; ng++) {
        int col = h * DHEAD + ng * 8 + ec;
        size_t o1 = ((size_t)b * SEQ + gq) * DMODEL + col;
        size_t o2 = ((size_t)b * SEQ + gq + 8) * DMODEL + col;
        *(uint32_t*)(O + o1) = pack_half(of[ng][0] * inv1, of[ng][1] * inv1);
        *(uint32_t*)(O + o2) = pack_half(of[ng][2] * inv2, of[ng][3] * inv2);
    }
}

// ---------------------------------------------------------------------------
// Orchestration — 4th launch (ncu capture slot) = fused qkv GEMM.
// ---------------------------------------------------------------------------
extern "C" void kernel_launch(void* const* d_in, const int* in_sizes, int n_in,
                              void* d_out, int out_size)
{
    const float* x     = (const float*)d_in[0];
    const float* enc   = (const float*)d_in[1];
    const float* sa_wq = (const float*)d_in[4];
    const float* sa_wk = (const float*)d_in[5];
    const float* sa_wv = (const float*)d_in[6];
    const float* sa_wo = (const float*)d_in[7];
    const float* sa_bo = (const float*)d_in[8];
    const float* ca_wq = (const float*)d_in[9];
    const float* ca_wk = (const float*)d_in[10];
    const float* ca_wv = (const float*)d_in[11];
    const float* ca_wo = (const float*)d_in[12];
    const float* ca_bo = (const float*)d_in[13];
    const float* ff_w1 = (const float*)d_in[14];
    const float* ff_b1 = (const float*)d_in[15];
    const float* ff_w2 = (const float*)d_in[16];
    const float* ff_b2 = (const float*)d_in[17];
    const float* ln0_g = (const float*)d_in[18];
    const float* ln0_b = (const float*)d_in[19];
    const float* ln1_g = (const float*)d_in[20];
    const float* ln1_b = (const float*)d_in[21];
    const float* ln2_g = (const float*)d_in[22];
    const float* ln2_b = (const float*)d_in[23];
    float* out = (float*)d_out;

    uint16_t *h, *qb, *qkv, *kv, *att, *ench, *ff, *w;
    float *x1, *x2;
    cudaGetSymbolAddress((void**)&h,    g_h);
    cudaGetSymbolAddress((void**)&qb,   g_q);
    cudaGetSymbolAddress((void**)&qkv,  g_qkv);
    cudaGetSymbolAddress((void**)&kv,   g_kv);
    cudaGetSymbolAddress((void**)&att,  g_att);
    cudaGetSymbolAddress((void**)&ench, g_enc);
    cudaGetSymbolAddress((void**)&x1,   g_x1);
    cudaGetSymbolAddress((void**)&x2,   g_x2);
    cudaGetSymbolAddress((void**)&ff,   g_ff);
    cudaGetSymbolAddress((void**)&w,    g_w);

    cudaFuncSetAttribute(attn_v3<true>,  cudaFuncAttributeMaxDynamicSharedMemorySize, ATT3_SMEM);
    cudaFuncSetAttribute(attn_v3<false>, cudaFuncAttributeMaxDynamicSharedMemorySize, ATT3_SMEM);
    cudaFuncSetAttribute(gemm_v5<1, false, false, false>, cudaFuncAttributeMaxDynamicSharedMemorySize, GSMEM);
    cudaFuncSetAttribute(gemm_v5<0, true, true, false>,   cudaFuncAttributeMaxDynamicSharedMemorySize, GSMEM);
    cudaFuncSetAttribute(gemm_v5<1, true, false, true>,   cudaFuncAttributeMaxDynamicSharedMemorySize, GSMEM);

    dim3 cb(32, 8);
    WPtrs8 ws;
    ws.p[0] = sa_wq; ws.p[1] = sa_wk; ws.p[2] = sa_wv; ws.p[3] = sa_wo;
    ws.p[4] = ca_wq; ws.p[5] = ca_wk; ws.p[6] = ca_wv; ws.p[7] = ca_wo;

    dim3 gqkv(3 * DMODEL / 128, MROWS / 128);  // (12, 64)
    dim3 gkv(2 * DMODEL / 128, MROWS / 128);   // (8, 64)
    dim3 gproj(DMODEL / 128, MROWS / 128);     // (4, 64)
    dim3 gff1(DFF / 128, MROWS / 128);         // (16, 64)
    dim3 gattn(SEQ / 128, NHEAD, BATCH);       // (16, 8, 4)

    // Launch 1-3: proj weight conv, enc split, LN0
    wconv8_kernel<<<dim3(16, 16, 8), cb>>>(ws, w);
    split_kernel<<<MROWS, 128>>>(enc, ench);
    ln_kernel<<<MROWS, 128>>>(x, ln0_g, ln0_b, h);

    // Launch 4 (ncu capture slot): fused qkv GEMM
    gemm_v5<1, false, false, false><<<gqkv, 256, GSMEM>>>(h, w, nullptr, nullptr, nullptr, qkv, MROWS, 3 * DMODEL, DMODEL);
    attn_v3<true><<<gattn, 256, ATT3_SMEM>>>(qkv, 3 * DMODEL,
                                             qkv + DMODEL, 3 * DMODEL,
                                             qkv + 2 * DMODEL, 3 * DMODEL, att);
    gemm_v5<0, true, true, false><<<gproj, 256, GSMEM>>>(att, w + 3 * 262144, sa_bo, x, x1, nullptr, MROWS, DMODEL, DMODEL);

    // --- Cross-attention block ---
    ln_kernel<<<MROWS, 128>>>(x1, ln1_g, ln1_b, h);
    gemm_v5<1, false, false, false><<<gproj, 256, GSMEM>>>(h, w + 4 * 262144, nullptr, nullptr, nullptr, qb, MROWS, DMODEL, DMODEL);
    gemm_v5<1, false, false, false><<<gkv, 256, GSMEM>>>(ench, w + 5 * 262144, nullptr, nullptr, nullptr, kv, MROWS, 2 * DMODEL, DMODEL);
    attn_v3<false><<<gattn, 256, ATT3_SMEM>>>(qb, DMODEL,
                                              kv, 2 * DMODEL,
                                              kv + DMODEL, 2 * DMODEL, att);
    gemm_v5<0, true, true, false><<<gproj, 256, GSMEM>>>(att, w + 7 * 262144, ca_bo, x1, x2, nullptr, MROWS, DMODEL, DMODEL);

    // --- Feed-forward block ---
    wconv_kernel<<<dim3(64, 16), cb>>>(ff_w1, w + WOFF_FF1, 512, 2048);
    wconv_kernel<<<dim3(16, 64), cb>>>(ff_w2, w + WOFF_FF2, 2048, 512);
    ln_kernel<<<MROWS, 128>>>(x2, ln2_g, ln2_b, h);
    gemm_v5<1, true, false, true><<<gff1, 256, GSMEM>>>(h, w + WOFF_FF1, ff_b1, nullptr, nullptr, ff, MROWS, DFF, DMODEL);
    gemm_v5<0, true, true, false><<<gproj, 256, GSMEM>>>(ff, w + WOFF_FF2, ff_b2, x2, out, nullptr, MROWS, DMODEL, DFF);
}

// round 14
// speedup vs baseline: 1.0341x; 1.0341x over previous
#include <cuda_runtime.h>
#include <cuda_fp16.h>
#include <cstdint>
#include <math.h>

// Problem constants
#define BATCH 4
#define SEQ   2048
#define DMODEL 512
#define NHEAD 8
#define DHEAD 64
#define DFF   2048
#define MROWS (BATCH * SEQ)   // 8192

// ---------------------------------------------------------------------------
// Scratch (allocation-free: __device__ globals) — activations fp16
// ---------------------------------------------------------------------------
__device__ uint16_t g_h  [(size_t)MROWS * DMODEL];
__device__ uint16_t g_q  [(size_t)MROWS * DMODEL];
__device__ uint16_t g_qkv[(size_t)MROWS * (3 * DMODEL)];   // fused q|k|v, stride 1536
__device__ uint16_t g_kv [(size_t)MROWS * (2 * DMODEL)];   // fused k|v, stride 1024
__device__ uint16_t g_att[(size_t)MROWS * DMODEL];
__device__ uint16_t g_enc[(size_t)MROWS * DMODEL];
__device__ float    g_x1 [(size_t)MROWS * DMODEL];
__device__ float    g_x2 [(size_t)MROWS * DMODEL];
__device__ uint16_t g_ff [(size_t)MROWS * DFF];
// converted weights, fp16 [N][K]: 8x 512x512, ff1(2048x512), ff2(512x2048)
#define WOFF_FF1 2097152
#define WOFF_FF2 3145728
__device__ uint16_t g_w[4194304];

// ---------------------------------------------------------------------------
// Helpers
// ---------------------------------------------------------------------------
__device__ __forceinline__ uint32_t smem_u32(const void* p) {
    uint32_t a;
    asm("{ .reg .u64 t; cvta.to.shared.u64 t, %1; cvt.u32.u64 %0, t; }"
        : "=r"(a) : "l"(p));
    return a;
}

__device__ __forceinline__ void ldm_x4(uint32_t* r, const void* p) {
    uint32_t a = smem_u32(p);
    asm volatile("ldmatrix.sync.aligned.m8n8.x4.shared.b16 {%0,%1,%2,%3}, [%4];"
        : "=r"(r[0]), "=r"(r[1]), "=r"(r[2]), "=r"(r[3]) : "r"(a));
}

// D += A(16x16,row) * B(16x8,col)  fp16 in, fp32 acc
__device__ __forceinline__ void mma_f16(float* d, const uint32_t* a,
                                        uint32_t b0, uint32_t b1) {
    asm("mma.sync.aligned.m16n8k16.row.col.f32.f16.f16.f32 "
        "{%0,%1,%2,%3}, {%4,%5,%6,%7}, {%8,%9}, {%0,%1,%2,%3};"
        : "+f"(d[0]), "+f"(d[1]), "+f"(d[2]), "+f"(d[3])
        : "r"(a[0]), "r"(a[1]), "r"(a[2]), "r"(a[3]), "r"(b0), "r"(b1));
}

// D += A * B, fp16 in, fp16 acc (d = 2x uint32 = 4 halves)
__device__ __forceinline__ void mma_f16acc(uint32_t* d, const uint32_t* a,
                                           uint32_t b0, uint32_t b1) {
    asm("mma.sync.aligned.m16n8k16.row.col.f16.f16.f16.f16 "
        "{%0,%1}, {%2,%3,%4,%5}, {%6,%7}, {%0,%1};"
        : "+r"(d[0]), "+r"(d[1])
        : "r"(a[0]), "r"(a[1]), "r"(a[2]), "r"(a[3]), "r"(b0), "r"(b1));
}

__device__ __forceinline__ void cp16(uint32_t dst, const void* src) {
    asm volatile("cp.async.cg.shared.global [%0], [%1], 16;" :: "r"(dst), "l"(src));
}
#define CP_COMMIT() asm volatile("cp.async.commit_group;" ::: "memory")
#define CP_WAIT2()  asm volatile("cp.async.wait_group 2;" ::: "memory")

__device__ __forceinline__ uint32_t pack_half(float a, float b) {
    __half2 h = __floats2half2_rn(a, b);
    return *reinterpret_cast<uint32_t*>(&h);
}

__device__ __forceinline__ float2 unpack_half(uint32_t v) {
    __half2 h = *reinterpret_cast<__half2*>(&v);
    return __half22float2(h);
}

__device__ __forceinline__ uint2 cvt4_half(float4 a) {
    uint2 r;
    r.x = pack_half(a.x, a.y);
    r.y = pack_half(a.z, a.w);
    return r;
}

// Fast exp on FMA/ALU pipes (no MUFU). ~2e-6 rel err.
__device__ __forceinline__ float fexp(float x) {
    x = fmaxf(x, -80.f);
    float t = fmaf(x, 1.442695041f, 12582912.f);
    int   n = __float_as_int(t) - 0x4B400000;
    float i_f = t - 12582912.f;
    float f = fmaf(x, 1.442695041f, -i_f);
    float p = 0.0013333558f;
    p = fmaf(p, f, 0.0096181291f);
    p = fmaf(p, f, 0.0555041087f);
    p = fmaf(p, f, 0.2402265069f);
    p = fmaf(p, f, 0.6931471806f);
    p = fmaf(p, f, 1.0f);
    return __int_as_float(__float_as_int(p) + (n << 23));
}

// ---------------------------------------------------------------------------
// Weight conversion: W[K][N] fp32 -> [N][K] fp16
// ---------------------------------------------------------------------------
struct WPtrs8 { const float* p[8]; };

__global__ void wconv8_kernel(WPtrs8 ws, uint16_t* __restrict__ Wh)
{
    __shared__ float tile[32][33];
    const int K = 512, N = 512;
    const float* W = ws.p[blockIdx.z];
    uint16_t* wh = Wh + (size_t)blockIdx.z * 262144;
    int n0 = blockIdx.x * 32, k0 = blockIdx.y * 32;
    int tx = threadIdx.x, ty = threadIdx.y;
    #pragma unroll
    for (int i = 0; i < 4; i++)
        tile[ty + i * 8][tx] = W[(size_t)(k0 + ty + i * 8) * N + n0 + tx];
    __syncthreads();
    #pragma unroll
    for (int i = 0; i < 4; i++) {
        int n = ty + i * 8;
        wh[(size_t)(n0 + n) * K + k0 + tx] =
            __half_as_ushort(__float2half_rn(tile[tx][n]));
    }
}

__global__ void wconv_kernel(const float* __restrict__ W,
                             uint16_t* __restrict__ Wh, int K, int N)
{
    __shared__ float tile[32][33];
    int n0 = blockIdx.x * 32, k0 = blockIdx.y * 32;
    int tx = threadIdx.x, ty = threadIdx.y;
    #pragma unroll
    for (int i = 0; i < 4; i++)
        tile[ty + i * 8][tx] = W[(size_t)(k0 + ty + i * 8) * N + n0 + tx];
    __syncthreads();
    #pragma unroll
    for (int i = 0; i < 4; i++) {
        int n = ty + i * 8;
        Wh[(size_t)(n0 + n) * K + k0 + tx] =
            __half_as_ushort(__float2half_rn(tile[tx][n]));
    }
}

// fp32 activations -> fp16 (identity, for encoder_output)
__global__ void split_kernel(const float* __restrict__ x,
                             uint16_t* __restrict__ out)
{
    int row = blockIdx.x;
    int t = threadIdx.x;  // 0..127
    const float4 v = ((const float4*)(x + (size_t)row * DMODEL))[t];
    *(uint2*)(out + (size_t)row * DMODEL + t * 4) = cvt4_half(v);
}

// ---------------------------------------------------------------------------
// LayerNorm -> fp16 output
// ---------------------------------------------------------------------------
__global__ void ln_kernel(const float* __restrict__ x,
                          const float* __restrict__ g,
                          const float* __restrict__ b,
                          uint16_t* __restrict__ out)
{
    int row = blockIdx.x;
    int t = threadIdx.x;  // 0..127
    const float4 v = ((const float4*)(x + (size_t)row * DMODEL))[t];

    __shared__ float red1[4], red2[4];

    float s = v.x + v.y + v.z + v.w;
    #pragma unroll
    for (int o = 16; o; o >>= 1) s += __shfl_xor_sync(0xffffffffu, s, o);
    if ((t & 31) == 0) red1[t >> 5] = s;
    __syncthreads();
    float mean = (red1[0] + red1[1] + red1[2] + red1[3]) * (1.0f / DMODEL);

    float d0 = v.x - mean, d1 = v.y - mean, d2 = v.z - mean, d3 = v.w - mean;
    float sq = d0*d0 + d1*d1 + d2*d2 + d3*d3;
    #pragma unroll
    for (int o = 16; o; o >>= 1) sq += __shfl_xor_sync(0xffffffffu, sq, o);
    if ((t & 31) == 0) red2[t >> 5] = sq;
    __syncthreads();
    float var = (red2[0] + red2[1] + red2[2] + red2[3]) * (1.0f / (DMODEL - 1));
    float rstd = 1.0f / (sqrtf(var) + 1e-6f);

    const float4 gv = ((const float4*)g)[t];
    const float4 bv = ((const float4*)b)[t];
    float4 o4;
    o4.x = gv.x * d0 * rstd + bv.x;
    o4.y = gv.y * d1 * rstd + bv.y;
    o4.z = gv.z * d2 * rstd + bv.z;
    o4.w = gv.w * d3 * rstd + bv.w;
    *(uint2*)(out + (size_t)row * DMODEL + t * 4) = cvt4_half(o4);
}

// ---------------------------------------------------------------------------
// GEMM v5 (best measured): 128x128 tile, BK=32, fp16 in, fp32 acc,
// 3-stage cp.async, B-fragment ping-pong.
// ---------------------------------------------------------------------------
#define LDA 40
#define GSMEM (3 * 20480)

template<int OUT, bool BIAS, bool RES, bool RELU>
__global__ void __launch_bounds__(256, 2)
gemm_v5(const uint16_t* __restrict__ A_g, const uint16_t* __restrict__ B_g,
        const float* __restrict__ bias, const float* __restrict__ res,
        float* __restrict__ Cf, uint16_t* __restrict__ Ch,
        int M, int N, int K)
{
    extern __shared__ char smem[];
    const uint32_t sbase = smem_u32(smem);

    const int tid  = threadIdx.x;
    const int lane = tid & 31;
    const int wid  = tid >> 5;
    const int m0 = blockIdx.y * 128;
    const int n0 = blockIdx.x * 128;
    const int wm = (wid >> 1) * 32;
    const int wn = (wid & 1) * 64;
    const int KT = K >> 5;

    float acc[2][8][4];
    #pragma unroll
    for (int i = 0; i < 2; i++)
        #pragma unroll
        for (int j = 0; j < 8; j++)
            #pragma unroll
            for (int c = 0; c < 4; c++) acc[i][j][c] = 0.f;

    const int lrow = tid >> 1;
    const int lc0  = (tid & 1) * 2;

    auto issue = [&](int kt) {
        int st = kt % 3;
        uint32_t base = sbase + st * 20480;
        size_t aoff = (size_t)(m0 + lrow) * K + kt * 32 + lc0 * 8;
        size_t boff = (size_t)(n0 + lrow) * K + kt * 32 + lc0 * 8;
        uint32_t d = base + lrow * 80 + lc0 * 16;
        cp16(d,              A_g + aoff);
        cp16(d + 16,         A_g + aoff + 8);
        cp16(d + 10240,      B_g + boff);
        cp16(d + 10240 + 16, B_g + boff + 8);
    };

    issue(0);
    CP_COMMIT();
    if (KT > 1) issue(1);
    CP_COMMIT();

    const int lr = lane & 15;
    const int lh = (lane >> 4) * 8;

    for (int kt = 0; kt < KT; kt++) {
        if (kt + 2 < KT) issue(kt + 2);
        CP_COMMIT();
        CP_WAIT2();
        __syncthreads();

        const uint16_t* As = (const uint16_t*)(smem + (kt % 3) * 20480);
        const uint16_t* Bs = As + 5120;

        #pragma unroll
        for (int ks = 0; ks < 32; ks += 16) {
            uint32_t af[2][4];
            #pragma unroll
            for (int mi = 0; mi < 2; mi++)
                ldm_x4(af[mi], As + (wm + mi * 16 + lr) * LDA + ks + lh);

            uint32_t bf[2][4];
            ldm_x4(bf[0], Bs + (wn + lr) * LDA + ks + lh);
            #pragma unroll
            for (int ni = 0; ni < 4; ni++) {
                const int cur = ni & 1;
                if (ni < 3)
                    ldm_x4(bf[cur ^ 1], Bs + (wn + (ni + 1) * 16 + lr) * LDA + ks + lh);
                #pragma unroll
                for (int mi = 0; mi < 2; mi++) {
                    mma_f16(acc[mi][ni * 2],     af[mi], bf[cur][0], bf[cur][2]);
                    mma_f16(acc[mi][ni * 2 + 1], af[mi], bf[cur][1], bf[cur][3]);
                }
            }
        }
        __syncthreads();
    }

    const int er = lane >> 2;
    const int ec = (lane & 3) * 2;
    #pragma unroll
    for (int mi = 0; mi < 2; mi++) {
        #pragma unroll
        for (int nf = 0; nf < 8; nf++) {
            int gm0 = m0 + wm + mi * 16 + er;
            int gn  = n0 + wn + nf * 8 + ec;
            #pragma unroll
            for (int half = 0; half < 2; half++) {
                int gm = gm0 + half * 8;
                float cx = acc[mi][nf][half * 2];
                float cy = acc[mi][nf][half * 2 + 1];
                if (BIAS) { cx += bias[gn]; cy += bias[gn + 1]; }
                if (RES) {
                    const float2 rv = *(const float2*)(res + (size_t)gm * N + gn);
                    cx += rv.x; cy += rv.y;
                }
                if (RELU) { cx = fmaxf(cx, 0.f); cy = fmaxf(cy, 0.f); }
                size_t idx = (size_t)gm * N + gn;
                if (OUT == 0) {
                    *(float2*)(Cf + idx) = make_float2(cx, cy);
                } else {
                    *(uint32_t*)(Ch + idx) = pack_half(cx, cy);
                }
            }
        }
    }
}

// ---------------------------------------------------------------------------
// Flash attention (R10 config — best measured): fp16 in (strided q/k/v),
// fp16 out. QK f16 accumulation; PV fp32 acc. Reversed causal mapping.
// ---------------------------------------------------------------------------
#define QLD 72
#define PLD 136
#define ATT2_SMEM 92672

template<bool CAUSAL>
__global__ void __launch_bounds__(256, 2)
attn_mma(const uint16_t* __restrict__ Q, int ldq,
         const uint16_t* __restrict__ K, int ldk,
         const uint16_t* __restrict__ V, int ldv,
         uint16_t* __restrict__ O)
{
    extern __shared__ char asmem[];
    uint16_t* Qs = (uint16_t*)(asmem);
    uint16_t* Ks = (uint16_t*)(asmem + 18432);
    uint16_t* Vt = (uint16_t*)(asmem + 36864);
    uint16_t* Ps = (uint16_t*)(asmem + 54272);
    float* part_max = (float*)(asmem + 89088);
    float* part_sum = (float*)(asmem + 90112);
    float* mrow = (float*)(asmem + 91136);
    float* lrow = (float*)(asmem + 91648);
    float* arow = (float*)(asmem + 92160);

    const int tid  = threadIdx.x;
    const int lane = tid & 31;
    const int wid  = tid >> 5;
    const int wm   = (wid >> 1) * 32;
    const int wnk  = (wid & 1) * 64;
    const int wnd  = (wid & 1) * 32;
    const int er   = lane >> 2;
    const int ec   = (lane & 3) * 2;
    const int lr   = lane & 15;
    const int lh   = (lane >> 4) * 8;

    const int qt = CAUSAL ? ((int)gridDim.x - 1 - (int)blockIdx.x) : (int)blockIdx.x;
    const int q0 = qt * 128;
    const int h  = blockIdx.y;
    const int b  = blockIdx.z;

    const size_t bq = ((size_t)b * SEQ + q0) * ldq + (size_t)h * DHEAD;
    const size_t bk = ((size_t)b * SEQ) * ldk + (size_t)h * DHEAD;
    const size_t bvo = ((size_t)b * SEQ) * ldv + (size_t)h * DHEAD;

    #pragma unroll
    for (int it = 0; it < 4; it++) {
        int vI = tid + it * 256;
        int row = vI >> 3, c8 = vI & 7;
        uint4 qv = *(const uint4*)(Q + bq + (size_t)row * ldq + c8 * 8);
        *(uint4*)(Qs + row * QLD + c8 * 8) = qv;
    }
    if (tid < 128) { mrow[tid] = -INFINITY; lrow[tid] = 0.f; }

    float o[2][4][4];
    #pragma unroll
    for (int mi = 0; mi < 2; mi++)
        #pragma unroll
        for (int nf = 0; nf < 4; nf++)
            #pragma unroll
            for (int c = 0; c < 4; c++) o[mi][nf][c] = 0.f;

    __syncthreads();

    const int ntiles = CAUSAL ? (qt + 1) : (SEQ / 128);

    for (int t = 0; t < ntiles; t++) {
        const int j0 = t * 128;

        #pragma unroll
        for (int it = 0; it < 4; it++) {
            int vI = tid + it * 256;
            int row = vI >> 3, c8 = vI & 7;
            uint4 kv = *(const uint4*)(K + bk + (size_t)(j0 + row) * ldk + c8 * 8);
            *(uint4*)(Ks + row * QLD + c8 * 8) = kv;
        }
        __syncthreads();  // (A)

        uint32_t sch[2][8][2];
        #pragma unroll
        for (int mi = 0; mi < 2; mi++)
            #pragma unroll
            for (int nf = 0; nf < 8; nf++) { sch[mi][nf][0] = 0u; sch[mi][nf][1] = 0u; }

        #pragma unroll
        for (int ks = 0; ks < 64; ks += 16) {
            uint32_t aq[2][4];
            #pragma unroll
            for (int mi = 0; mi < 2; mi++)
                ldm_x4(aq[mi], Qs + (wm + mi * 16 + lr) * QLD + ks + lh);

            uint32_t bkf[2][4];
            ldm_x4(bkf[0], Ks + (wnk + lr) * QLD + ks + lh);
            #pragma unroll
            for (int ni = 0; ni < 4; ni++) {
                const int cur = ni & 1;
                if (ni < 3)
                    ldm_x4(bkf[cur ^ 1], Ks + (wnk + (ni + 1) * 16 + lr) * QLD + ks + lh);
                #pragma unroll
                for (int mi = 0; mi < 2; mi++) {
                    mma_f16acc(sch[mi][ni * 2],     aq[mi], bkf[cur][0], bkf[cur][2]);
                    mma_f16acc(sch[mi][ni * 2 + 1], aq[mi], bkf[cur][1], bkf[cur][3]);
                }
            }
        }

        #pragma unroll
        for (int it = 0; it < 8; it++) {
            int vI = tid + it * 256;
            int row = vI >> 4, c4 = vI & 15;
            uint2 vv = *(const uint2*)(V + bvo + (size_t)(j0 + row) * ldv + c4 * 4);
            Vt[(c4 * 4 + 0) * PLD + row] = (uint16_t)(vv.x & 0xffff);
            Vt[(c4 * 4 + 1) * PLD + row] = (uint16_t)(vv.x >> 16);
            Vt[(c4 * 4 + 2) * PLD + row] = (uint16_t)(vv.y & 0xffff);
            Vt[(c4 * 4 + 3) * PLD + row] = (uint16_t)(vv.y >> 16);
        }

        float sc[2][8][4];
        float lm[2][2] = {{-INFINITY, -INFINITY}, {-INFINITY, -INFINITY}};
        #pragma unroll
        for (int mi = 0; mi < 2; mi++) {
            #pragma unroll
            for (int nf = 0; nf < 8; nf++) {
                float2 lo = unpack_half(sch[mi][nf][0]);
                float2 hi = unpack_half(sch[mi][nf][1]);
                float vals[4] = {lo.x, lo.y, hi.x, hi.y};
                #pragma unroll
                for (int c = 0; c < 4; c++) {
                    float val = vals[c] * 0.125f;
                    if (CAUSAL && t == qt) {
                        int gq = q0 + wm + mi * 16 + er + (c >> 1) * 8;
                        int gj = j0 + wnk + nf * 8 + ec + (c & 1);
                        if (gj > gq) val = -1e9f;
                    }
                    sc[mi][nf][c] = val;
                    lm[mi][c >> 1] = fmaxf(lm[mi][c >> 1], val);
                }
            }
        }
        #pragma unroll
        for (int mi = 0; mi < 2; mi++)
            #pragma unroll
            for (int hh = 0; hh < 2; hh++) {
                float v2 = lm[mi][hh];
                v2 = fmaxf(v2, __shfl_xor_sync(0xffffffffu, v2, 1));
                v2 = fmaxf(v2, __shfl_xor_sync(0xffffffffu, v2, 2));
                lm[mi][hh] = v2;
            }
        if ((lane & 3) == 0) {
            part_max[wid * 32 + 0 * 16 + 0 * 8 + er] = lm[0][0];
            part_max[wid * 32 + 0 * 16 + 1 * 8 + er] = lm[0][1];
            part_max[wid * 32 + 1 * 16 + 0 * 8 + er] = lm[1][0];
            part_max[wid * 32 + 1 * 16 + 1 * 8 + er] = lm[1][1];
        }
        __syncthreads();  // (B)

        if (tid < 128) {
            int g = tid >> 5, rr = tid & 31;
            float pm = fmaxf(part_max[(2 * g) * 32 + rr], part_max[(2 * g + 1) * 32 + rr]);
            float mo = mrow[tid];
            float mn = fmaxf(mo, pm);
            float al = fexp(mo - mn);
            arow[tid] = al;
            mrow[tid] = mn;
            lrow[tid] *= al;
        }
        __syncthreads();  // (C)

        float ls[2][2] = {{0.f, 0.f}, {0.f, 0.f}};
        #pragma unroll
        for (int mi = 0; mi < 2; mi++) {
            float m1 = mrow[wm + mi * 16 + er];
            float m2 = mrow[wm + mi * 16 + er + 8];
            #pragma unroll
            for (int nf = 0; nf < 8; nf++) {
                float p0 = fexp(sc[mi][nf][0] - m1);
                float p1 = fexp(sc[mi][nf][1] - m1);
                float p2 = fexp(sc[mi][nf][2] - m2);
                float p3 = fexp(sc[mi][nf][3] - m2);
                ls[mi][0] += p0 + p1;
                ls[mi][1] += p2 + p3;
                int col = wnk + nf * 8 + ec;
                *(uint32_t*)(Ps + (wm + mi * 16 + er) * PLD + col)     = pack_half(p0, p1);
                *(uint32_t*)(Ps + (wm + mi * 16 + er + 8) * PLD + col) = pack_half(p2, p3);
            }
        }
        #pragma unroll
        for (int mi = 0; mi < 2; mi++)
            #pragma unroll
            for (int hh = 0; hh < 2; hh++) {
                float v2 = ls[mi][hh];
                v2 += __shfl_xor_sync(0xffffffffu, v2, 1);
                v2 += __shfl_xor_sync(0xffffffffu, v2, 2);
                ls[mi][hh] = v2;
            }
        if ((lane & 3) == 0) {
            part_sum[wid * 32 + 0 * 16 + 0 * 8 + er] = ls[0][0];
            part_sum[wid * 32 + 0 * 16 + 1 * 8 + er] = ls[0][1];
            part_sum[wid * 32 + 1 * 16 + 0 * 8 + er] = ls[1][0];
            part_sum[wid * 32 + 1 * 16 + 1 * 8 + er] = ls[1][1];
        }

        #pragma unroll
        for (int mi = 0; mi < 2; mi++) {
            float a1 = arow[wm + mi * 16 + er];
            float a2 = arow[wm + mi * 16 + er + 8];
            #pragma unroll
            for (int nf = 0; nf < 4; nf++) {
                o[mi][nf][0] *= a1; o[mi][nf][1] *= a1;
                o[mi][nf][2] *= a2; o[mi][nf][3] *= a2;
            }
        }
        __syncthreads();  // (D)

        if (tid < 128) {
            int g = tid >> 5, rr = tid & 31;
            lrow[tid] += part_sum[(2 * g) * 32 + rr] + part_sum[(2 * g + 1) * 32 + rr];
        }

        #pragma unroll
        for (int ks = 0; ks < 128; ks += 16) {
            uint32_t ap[2][4];
            #pragma unroll
            for (int mi = 0; mi < 2; mi++)
                ldm_x4(ap[mi], Ps + (wm + mi * 16 + lr) * PLD + ks + lh);

            uint32_t bvf[2][4];
            ldm_x4(bvf[0], Vt + (wnd + lr) * PLD + ks + lh);
            #pragma unroll
            for (int ni = 0; ni < 2; ni++) {
                const int cur = ni & 1;
                if (ni < 1)
                    ldm_x4(bvf[cur ^ 1], Vt + (wnd + 16 + lr) * PLD + ks + lh);
                #pragma unroll
                for (int mi = 0; mi < 2; mi++) {
                    mma_f16(o[mi][ni * 2],     ap[mi], bvf[cur][0], bvf[cur][2]);
                    mma_f16(o[mi][ni * 2 + 1], ap[mi], bvf[cur][1], bvf[cur][3]);
                }
            }
        }
    }

    __syncthreads();

    #pragma unroll
    for (int mi = 0; mi < 2; mi++) {
        float inv1 = 1.0f / lrow[wm + mi * 16 + er];
        float inv2 = 1.0f / lrow[wm + mi * 16 + er + 8];
        #pragma unroll
        for (int nf = 0; nf < 4; nf++) {
            int gq1 = q0 + wm + mi * 16 + er;
            int col = h * DHEAD + wnd + nf * 8 + ec;
            size_t o1 = ((size_t)b * SEQ + gq1) * DMODEL + col;
            size_t o2 = ((size_t)b * SEQ + gq1 + 8) * DMODEL + col;
            *(uint32_t*)(O + o1) = pack_half(o[mi][nf][0] * inv1, o[mi][nf][1] * inv1);
            *(uint32_t*)(O + o2) = pack_half(o[mi][nf][2] * inv2, o[mi][nf][3] * inv2);
        }
    }
}

// ---------------------------------------------------------------------------
// Orchestration — 4th launch (ncu capture slot) = fused qkv GEMM.
// ---------------------------------------------------------------------------
extern "C" void kernel_launch(void* const* d_in, const int* in_sizes, int n_in,
                              void* d_out, int out_size)
{
    const float* x     = (const float*)d_in[0];
    const float* enc   = (const float*)d_in[1];
    const float* sa_wq = (const float*)d_in[4];
    const float* sa_wk = (const float*)d_in[5];
    const float* sa_wv = (const float*)d_in[6];
    const float* sa_wo = (const float*)d_in[7];
    const float* sa_bo = (const float*)d_in[8];
    const float* ca_wq = (const float*)d_in[9];
    const float* ca_wk = (const float*)d_in[10];
    const float* ca_wv = (const float*)d_in[11];
    const float* ca_wo = (const float*)d_in[12];
    const float* ca_bo = (const float*)d_in[13];
    const float* ff_w1 = (const float*)d_in[14];
    const float* ff_b1 = (const float*)d_in[15];
    const float* ff_w2 = (const float*)d_in[16];
    const float* ff_b2 = (const float*)d_in[17];
    const float* ln0_g = (const float*)d_in[18];
    const float* ln0_b = (const float*)d_in[19];
    const float* ln1_g = (const float*)d_in[20];
    const float* ln1_b = (const float*)d_in[21];
    const float* ln2_g = (const float*)d_in[22];
    const float* ln2_b = (const float*)d_in[23];
    float* out = (float*)d_out;

    uint16_t *h, *qb, *qkv, *kv, *att, *ench, *ff, *w;
    float *x1, *x2;
    cudaGetSymbolAddress((void**)&h,    g_h);
    cudaGetSymbolAddress((void**)&qb,   g_q);
    cudaGetSymbolAddress((void**)&qkv,  g_qkv);
    cudaGetSymbolAddress((void**)&kv,   g_kv);
    cudaGetSymbolAddress((void**)&att,  g_att);
    cudaGetSymbolAddress((void**)&ench, g_enc);
    cudaGetSymbolAddress((void**)&x1,   g_x1);
    cudaGetSymbolAddress((void**)&x2,   g_x2);
    cudaGetSymbolAddress((void**)&ff,   g_ff);
    cudaGetSymbolAddress((void**)&w,    g_w);

    cudaFuncSetAttribute(attn_mma<true>,  cudaFuncAttributeMaxDynamicSharedMemorySize, ATT2_SMEM);
    cudaFuncSetAttribute(attn_mma<false>, cudaFuncAttributeMaxDynamicSharedMemorySize, ATT2_SMEM);
    cudaFuncSetAttribute(gemm_v5<1, false, false, false>, cudaFuncAttributeMaxDynamicSharedMemorySize, GSMEM);
    cudaFuncSetAttribute(gemm_v5<0, true, true, false>,   cudaFuncAttributeMaxDynamicSharedMemorySize, GSMEM);
    cudaFuncSetAttribute(gemm_v5<1, true, false, true>,   cudaFuncAttributeMaxDynamicSharedMemorySize, GSMEM);

    dim3 cb(32, 8);
    WPtrs8 ws;
    ws.p[0] = sa_wq; ws.p[1] = sa_wk; ws.p[2] = sa_wv; ws.p[3] = sa_wo;
    ws.p[4] = ca_wq; ws.p[5] = ca_wk; ws.p[6] = ca_wv; ws.p[7] = ca_wo;

    dim3 gqkv(3 * DMODEL / 128, MROWS / 128);  // (12, 64)
    dim3 gkv(2 * DMODEL / 128, MROWS / 128);   // (8, 64)
    dim3 gproj(DMODEL / 128, MROWS / 128);     // (4, 64)
    dim3 gff1(DFF / 128, MROWS / 128);         // (16, 64)
    dim3 gattn(SEQ / 128, NHEAD, BATCH);       // (16, 8, 4)

    // Launch 1-3: proj weight conv, enc split, LN0
    wconv8_kernel<<<dim3(16, 16, 8), cb>>>(ws, w);
    split_kernel<<<MROWS, 128>>>(enc, ench);
    ln_kernel<<<MROWS, 128>>>(x, ln0_g, ln0_b, h);

    // Launch 4 (ncu capture slot): fused qkv GEMM
    gemm_v5<1, false, false, false><<<gqkv, 256, GSMEM>>>(h, w, nullptr, nullptr, nullptr, qkv, MROWS, 3 * DMODEL, DMODEL);
    attn_mma<true><<<gattn, 256, ATT2_SMEM>>>(qkv, 3 * DMODEL,
                                              qkv + DMODEL, 3 * DMODEL,
                                              qkv + 2 * DMODEL, 3 * DMODEL, att);
    gemm_v5<0, true, true, false><<<gproj, 256, GSMEM>>>(att, w + 3 * 262144, sa_bo, x, x1, nullptr, MROWS, DMODEL, DMODEL);

    // --- Cross-attention block ---
    ln_kernel<<<MROWS, 128>>>(x1, ln1_g, ln1_b, h);
    gemm_v5<1, false, false, false><<<gproj, 256, GSMEM>>>(h, w + 4 * 262144, nullptr, nullptr, nullptr, qb, MROWS, DMODEL, DMODEL);
    gemm_v5<1, false, false, false><<<gkv, 256, GSMEM>>>(ench, w + 5 * 262144, nullptr, nullptr, nullptr, kv, MROWS, 2 * DMODEL, DMODEL);
    attn_mma<false><<<gattn, 256, ATT2_SMEM>>>(qb, DMODEL,
                                               kv, 2 * DMODEL,
                                               kv + DMODEL, 2 * DMODEL, att);
    gemm_v5<0, true, true, false><<<gproj, 256, GSMEM>>>(att, w + 7 * 262144, ca_bo, x1, x2, nullptr, MROWS, DMODEL, DMODEL);

    // --- Feed-forward block ---
    wconv_kernel<<<dim3(64, 16), cb>>>(ff_w1, w + WOFF_FF1, 512, 2048);
    wconv_kernel<<<dim3(16, 64), cb>>>(ff_w2, w + WOFF_FF2, 2048, 512);
    ln_kernel<<<MROWS, 128>>>(x2, ln2_g, ln2_b, h);
    gemm_v5<1, true, false, true><<<gff1, 256, GSMEM>>>(h, w + WOFF_FF1, ff_b1, nullptr, nullptr, ff, MROWS, DFF, DMODEL);
    gemm_v5<0, true, true, false><<<gproj, 256, GSMEM>>>(ff, w + WOFF_FF2, ff_b2, x2, out, nullptr, MROWS, DMODEL, DFF);
}